// round 13
// baseline (speedup 1.0000x reference)
#include <cuda_runtime.h>
#include <cuda_fp16.h>
#include <math.h>
#include <stdint.h>

#define BATCH 32
#define TT 4096
#define DD 512
#define MM (BATCH * TT)

#define LDA 520          // A16 smem row stride in halves
#define LDB 136          // B16 smem row stride in halves

// ---------------- device scratch (no allocation allowed) -------------------
__device__ float g_e_t[MM];
__device__ float g_dec[BATCH * DD];
__device__ __half g_Wh16[DD * DD];   // fp16 copy of W_h [k][n]

// ---------------- smem layout (bytes) --------------------------------------
#define SM_A     0                       // 128 * LDA * 2 = 133120
#define SM_B0    133120                  // 32 * LDB * 2 = 8704
#define SM_B1    (SM_B0 + 8704)
#define SM_V     (SM_B1 + 8704)          // float[512]
#define SM_WC    (SM_V + 2048)
#define SM_DEC   (SM_WC + 2048)
#define SM_ESM   (SM_DEC + 2048)         // float[128]
#define SM_TOTAL (SM_ESM + 512 + 512)    // 157696

// ---------------- PTX helpers ----------------------------------------------
__device__ __forceinline__ uint32_t smem_u32(const void* p) {
    uint32_t a;
    asm("{ .reg .u64 t; cvta.to.shared.u64 t, %1; cvt.u32.u64 %0, t; }" : "=r"(a) : "l"(p));
    return a;
}
__device__ __forceinline__ void cp16(uint32_t dst, const void* src) {
    asm volatile("cp.async.cg.shared.global [%0], [%1], 16;" :: "r"(dst), "l"(src));
}
__device__ __forceinline__ void cp_commit() {
    asm volatile("cp.async.commit_group;" ::: "memory");
}
__device__ __forceinline__ void cp_wait1() {
    asm volatile("cp.async.wait_group 1;" ::: "memory");
}
__device__ __forceinline__ void cp_wait0() {
    asm volatile("cp.async.wait_group 0;" ::: "memory");
}
__device__ __forceinline__ float tanhap(float x) {
    float y; asm("tanh.approx.f32 %0, %1;" : "=f"(y) : "f"(x)); return y;
}
__device__ __forceinline__ void ldsm_x4(uint32_t* r, uint32_t addr) {
    asm volatile("ldmatrix.sync.aligned.m8n8.x4.shared.b16 {%0,%1,%2,%3}, [%4];"
                 : "=r"(r[0]), "=r"(r[1]), "=r"(r[2]), "=r"(r[3]) : "r"(addr));
}
__device__ __forceinline__ void ldsm_x4_t(uint32_t* r, uint32_t addr) {
    asm volatile("ldmatrix.sync.aligned.m8n8.x4.trans.shared.b16 {%0,%1,%2,%3}, [%4];"
                 : "=r"(r[0]), "=r"(r[1]), "=r"(r[2]), "=r"(r[3]) : "r"(addr));
}
// fp16-accumulate MMA: D(f16x2 x2) = A*B + D
__device__ __forceinline__ void mma_f16acc(uint32_t* c, const uint32_t* a, const uint32_t* b) {
    asm volatile(
        "mma.sync.aligned.m16n8k16.row.col.f16.f16.f16.f16 "
        "{%0,%1}, {%2,%3,%4,%5}, {%6,%7}, {%0,%1};"
        : "+r"(c[0]), "+r"(c[1])
        : "r"(a[0]), "r"(a[1]), "r"(a[2]), "r"(a[3]), "r"(b[0]), "r"(b[1]));
}

// ---------------------------------------------------------------------------
// Fused setup: blocks [0,1024) convert Wh -> fp16; blocks [1024,1088) compute
// dec_features and zero ctx.
// ---------------------------------------------------------------------------
__global__ __launch_bounds__(256) void setup_kernel(
    const float* __restrict__ Wh, const float* __restrict__ s,
    const float* __restrict__ Ws, const float* __restrict__ bs,
    float* __restrict__ ctx)
{
    int blk = blockIdx.x;
    if (blk < 1024) {
        int i = blk * 256 + threadIdx.x;
        g_Wh16[i] = __float2half(Wh[i]);
    } else {
        int idx = (blk - 1024) * 256 + threadIdx.x;
        int b = idx >> 9, e = idx & 511;
        float acc = bs[e];
        const float* sp = s + b * DD;
#pragma unroll 8
        for (int d = 0; d < DD; d++) acc += sp[d] * Ws[d * DD + e];
        g_dec[idx] = acc;
        ctx[idx] = 0.0f;
    }
}

// ---------------------------------------------------------------------------
// fp16 tensor-core score GEMM (f16 ACCUMULATE, fp32 promotion every 64 K),
// fused tanh/V-dot epilogue.
// CTA: 128 rows x full N=512, A resident fp16 in smem.
// 256 threads, 8 warps (2 M x 4 N), warp tile 64x32, BK=32 double-buffered B.
// ---------------------------------------------------------------------------
__global__ __launch_bounds__(256) void fused_score_gemm(
    const float* __restrict__ h, const float* __restrict__ cov,
    const float* __restrict__ Wc, const float* __restrict__ V)
{
    extern __shared__ char smem[];
    __half* A16 = (__half*)(smem + SM_A);
    float* sV   = (float*)(smem + SM_V);
    float* sWc  = (float*)(smem + SM_WC);
    float* sDec = (float*)(smem + SM_DEC);
    float* eSm  = (float*)(smem + SM_ESM);

    const int tid = threadIdx.x;
    const int lane = tid & 31, wid = tid >> 5;
    const int wm = wid >> 2, wn = wid & 3;           // 2 x 4 warp grid
    const int lr = lane >> 2, lc = lane & 3;
    const int row0 = blockIdx.x * 128;
    const int b = row0 >> 12;

    for (int i = tid; i < DD; i += 256) {
        sV[i] = V[i]; sWc[i] = Wc[i]; sDec[i] = g_dec[b * DD + i];
    }
    if (tid < 128) eSm[tid] = 0.0f;

    // ---- load h rows (fp32) -> convert -> resident fp16 A slab ------------
    {
        const float2* hp = (const float2*)(h + (size_t)row0 * DD);
#pragma unroll
        for (int i = 0; i < 128; i++) {
            int idx2 = tid + i * 256;
            int m = idx2 >> 8, c2 = idx2 & 255;
            float2 v = hp[(size_t)m * 256 + c2];
            *(__half2*)&A16[m * LDA + 2 * c2] = __floats2half2_rn(v.x, v.y);
        }
    }
    __syncthreads();

    const uint32_t sbB[2] = {smem_u32(smem + SM_B0), smem_u32(smem + SM_B1)};
    const uint32_t sbA = smem_u32(A16);

    float cvr[4][2];
#pragma unroll
    for (int mf = 0; mf < 4; mf++)
#pragma unroll
        for (int h2 = 0; h2 < 2; h2++)
            cvr[mf][h2] = cov[row0 + wm * 64 + mf * 16 + lr + h2 * 8];

    float acc_e[4][2];
#pragma unroll
    for (int mf = 0; mf < 4; mf++) { acc_e[mf][0] = 0.0f; acc_e[mf][1] = 0.0f; }

    // B tile loader: 32 k-rows x 128 n halves (8KB), 2 chunks of 16B/thread
    auto load_b = [&](int stage, int nb, int kt) {
#pragma unroll
        for (int i = 0; i < 2; i++) {
            int cid = tid + i * 256;                 // 0..511
            int k = cid >> 4, n8 = cid & 15;
            cp16(sbB[stage] + (k * LDB + n8 * 8) * 2,
                 g_Wh16 + (size_t)(kt * 32 + k) * DD + nb * 128 + n8 * 8);
        }
        cp_commit();
    };

    for (int nb = 0; nb < 4; nb++) {
        float acc[4][4][4];
        uint32_t hacc[4][4][2];
#pragma unroll
        for (int mf = 0; mf < 4; mf++)
#pragma unroll
            for (int nf = 0; nf < 4; nf++) {
#pragma unroll
                for (int c = 0; c < 4; c++) acc[mf][nf][c] = 0.0f;
                hacc[mf][nf][0] = 0u; hacc[mf][nf][1] = 0u;
            }

        load_b(0, nb, 0);

        for (int kt = 0; kt < 16; kt++) {
            if (kt + 1 < 16) { load_b((kt + 1) & 1, nb, kt + 1); cp_wait1(); }
            else             { cp_wait0(); }
            __syncthreads();

            const uint32_t B = sbB[kt & 1];
#pragma unroll
            for (int ks = 0; ks < 2; ks++) {
                const int k0 = kt * 32 + ks * 16;    // global k for A
                uint32_t a[4][4], bb[2][4];
#pragma unroll
                for (int mf = 0; mf < 4; mf++) {
                    int row = wm * 64 + mf * 16 + (lane & 15);
                    int col = k0 + ((lane >> 4) << 3);
                    ldsm_x4(a[mf], sbA + (row * LDA + col) * 2);
                }
#pragma unroll
                for (int p = 0; p < 2; p++) {
                    int krow = ks * 16 + (lane & 15);
                    int ncol = wn * 32 + p * 16 + ((lane >> 4) << 3);
                    ldsm_x4_t(bb[p], B + (krow * LDB + ncol) * 2);
                }
#pragma unroll
                for (int mf = 0; mf < 4; mf++) {
#pragma unroll
                    for (int p = 0; p < 2; p++) {
                        mma_f16acc(hacc[mf][2 * p],     a[mf], &bb[p][0]);
                        mma_f16acc(hacc[mf][2 * p + 1], a[mf], &bb[p][2]);
                    }
                }
            }
            __syncthreads();

            // promote f16 partial sums to fp32 every 2 chunks (64 K values)
            if (kt & 1) {
#pragma unroll
                for (int mf = 0; mf < 4; mf++) {
#pragma unroll
                    for (int nf = 0; nf < 4; nf++) {
                        float2 f0 = __half22float2(*(__half2*)&hacc[mf][nf][0]);
                        float2 f1 = __half22float2(*(__half2*)&hacc[mf][nf][1]);
                        acc[mf][nf][0] += f0.x; acc[mf][nf][1] += f0.y;
                        acc[mf][nf][2] += f1.x; acc[mf][nf][3] += f1.y;
                        hacc[mf][nf][0] = 0u;   hacc[mf][nf][1] = 0u;
                    }
                }
            }
        }

        // epilogue for this N-block: accumulate V . tanh(feat)
#pragma unroll
        for (int mf = 0; mf < 4; mf++) {
#pragma unroll
            for (int h2 = 0; h2 < 2; h2++) {
                float cv = cvr[mf][h2];
                float s = 0.0f;
#pragma unroll
                for (int nf = 0; nf < 4; nf++) {
#pragma unroll
                    for (int c2 = 0; c2 < 2; c2++) {
                        int nl = nb * 128 + wn * 32 + nf * 8 + 2 * lc + c2;
                        float f = acc[mf][nf][h2 * 2 + c2] + sDec[nl] + cv * sWc[nl];
                        s += sV[nl] * tanhap(f);
                    }
                }
                acc_e[mf][h2] += s;
            }
        }
    }

    // reduce across lc quad + wn warps via smem
#pragma unroll
    for (int mf = 0; mf < 4; mf++) {
#pragma unroll
        for (int h2 = 0; h2 < 2; h2++) {
            float s = acc_e[mf][h2];
            s += __shfl_xor_sync(0xffffffffu, s, 1, 4);
            s += __shfl_xor_sync(0xffffffffu, s, 2, 4);
            if (lc == 0)
                atomicAdd(&eSm[wm * 64 + mf * 16 + lr + h2 * 8], s);
        }
    }
    __syncthreads();
    if (tid < 128) g_e_t[row0 + tid] = eSm[tid];
}

// ---------------------------------------------------------------------------
__global__ __launch_bounds__(256) void softmax_kernel(
    const float* __restrict__ cov, float* __restrict__ a_out, float* __restrict__ ncov_out)
{
    int b = blockIdx.x;
    int tid = threadIdx.x;
    const float* e = g_e_t + b * TT;
    __shared__ float red[256];
    float ev[16];
    float m = -1e30f;
#pragma unroll
    for (int k = 0; k < 16; k++) { ev[k] = e[tid + k * 256]; m = fmaxf(m, ev[k]); }
    red[tid] = m; __syncthreads();
    for (int s = 128; s > 0; s >>= 1) {
        if (tid < s) red[tid] = fmaxf(red[tid], red[tid + s]);
        __syncthreads();
    }
    float M = red[0]; __syncthreads();
    float sum = 0.0f;
#pragma unroll
    for (int k = 0; k < 16; k++) { ev[k] = expf(ev[k] - M); sum += ev[k]; }
    red[tid] = sum; __syncthreads();
    for (int s = 128; s > 0; s >>= 1) {
        if (tid < s) red[tid] += red[tid + s];
        __syncthreads();
    }
    float inv = 1.0f / red[0];
#pragma unroll
    for (int k = 0; k < 16; k++) {
        int i = b * TT + tid + k * 256;
        float a = ev[k] * inv;
        a_out[i] = a;
        ncov_out[i] = cov[i] + a;
    }
}

// ---------------------------------------------------------------------------
// context[b][d] = sum_t a[b][t] * h[b][t][d]
// grid = B*64 T-chunks (2048 blocks), 128 threads, float4 per thread.
// ---------------------------------------------------------------------------
__global__ __launch_bounds__(128) void context_kernel(
    const float* __restrict__ h, const float* __restrict__ a, float* __restrict__ ctx)
{
    int b  = blockIdx.x >> 6;
    int tc = blockIdx.x & 63;
    int d4 = threadIdx.x;                 // float4 index 0..127
    int t0 = tc * 64;
    const float4* hp = (const float4*)(h + ((size_t)b * TT + t0) * DD) + d4;
    const float* ap = a + b * TT + t0;
    float4 acc = make_float4(0.f, 0.f, 0.f, 0.f);
#pragma unroll 8
    for (int t = 0; t < 64; t++) {
        float av = ap[t];
        float4 hv = hp[(size_t)t * 128];
        acc.x += av * hv.x; acc.y += av * hv.y;
        acc.z += av * hv.z; acc.w += av * hv.w;
    }
    float* c = &ctx[b * DD + d4 * 4];
    atomicAdd(c + 0, acc.x);
    atomicAdd(c + 1, acc.y);
    atomicAdd(c + 2, acc.z);
    atomicAdd(c + 3, acc.w);
}

// ---------------------------------------------------------------------------
extern "C" void kernel_launch(void* const* d_in, const int* in_sizes, int n_in,
                              void* d_out, int out_size)
{
    const float* h   = (const float*)d_in[0];
    const float* s   = (const float*)d_in[1];
    const float* cov = (const float*)d_in[2];
    const float* Wh  = (const float*)d_in[3];
    const float* Ws  = (const float*)d_in[4];
    const float* bs  = (const float*)d_in[5];
    const float* Wc  = (const float*)d_in[6];
    const float* V   = (const float*)d_in[7];

    float* out   = (float*)d_out;
    float* ctx   = out;
    float* a_out = out + BATCH * DD;
    float* ncov  = a_out + MM;

    cudaFuncSetAttribute(fused_score_gemm,
                         cudaFuncAttributeMaxDynamicSharedMemorySize, SM_TOTAL);

    setup_kernel<<<1088, 256>>>(Wh, s, Ws, bs, ctx);
    fused_score_gemm<<<MM / 128, 256, SM_TOTAL>>>(h, cov, Wc, V);
    softmax_kernel<<<BATCH, 256>>>(cov, a_out, ncov);
    context_kernel<<<BATCH * 64, 128>>>(h, a_out, ctx);
}

// round 14
// speedup vs baseline: 1.1373x; 1.1373x over previous
#include <cuda_runtime.h>
#include <cuda_fp16.h>
#include <math.h>
#include <stdint.h>

#define BATCH 32
#define TT 4096
#define DD 512
#define MM (BATCH * TT)

#define LDA 520          // A16 smem row stride in halves
#define LDB 136          // B16 smem row stride in halves

// ---------------- device scratch (no allocation allowed) -------------------
__device__ float g_e_t[MM];
__device__ float g_dec[BATCH * DD];
__device__ float2 g_stats[BATCH];    // per-batch (max, sum_exp)
__device__ __half g_Wh16[DD * DD];   // fp16 copy of W_h [k][n]

// ---------------- smem layout (bytes) --------------------------------------
#define SM_A     0                       // 128 * LDA * 2 = 133120
#define SM_B0    133120                  // 32 * LDB * 2 = 8704
#define SM_B1    (SM_B0 + 8704)
#define SM_V     (SM_B1 + 8704)          // float[512]
#define SM_WC    (SM_V + 2048)
#define SM_DEC   (SM_WC + 2048)
#define SM_ESM   (SM_DEC + 2048)         // float[128]
#define SM_TOTAL (SM_ESM + 512 + 512)    // 157696

// ---------------- PTX helpers ----------------------------------------------
__device__ __forceinline__ uint32_t smem_u32(const void* p) {
    uint32_t a;
    asm("{ .reg .u64 t; cvta.to.shared.u64 t, %1; cvt.u32.u64 %0, t; }" : "=r"(a) : "l"(p));
    return a;
}
__device__ __forceinline__ void cp16(uint32_t dst, const void* src) {
    asm volatile("cp.async.cg.shared.global [%0], [%1], 16;" :: "r"(dst), "l"(src));
}
__device__ __forceinline__ void cp_commit() {
    asm volatile("cp.async.commit_group;" ::: "memory");
}
__device__ __forceinline__ void cp_wait1() {
    asm volatile("cp.async.wait_group 1;" ::: "memory");
}
__device__ __forceinline__ void cp_wait0() {
    asm volatile("cp.async.wait_group 0;" ::: "memory");
}
__device__ __forceinline__ float tanhap(float x) {
    float y; asm("tanh.approx.f32 %0, %1;" : "=f"(y) : "f"(x)); return y;
}
__device__ __forceinline__ void ldsm_x4(uint32_t* r, uint32_t addr) {
    asm volatile("ldmatrix.sync.aligned.m8n8.x4.shared.b16 {%0,%1,%2,%3}, [%4];"
                 : "=r"(r[0]), "=r"(r[1]), "=r"(r[2]), "=r"(r[3]) : "r"(addr));
}
__device__ __forceinline__ void ldsm_x4_t(uint32_t* r, uint32_t addr) {
    asm volatile("ldmatrix.sync.aligned.m8n8.x4.trans.shared.b16 {%0,%1,%2,%3}, [%4];"
                 : "=r"(r[0]), "=r"(r[1]), "=r"(r[2]), "=r"(r[3]) : "r"(addr));
}
__device__ __forceinline__ void mma_f16(float* c, const uint32_t* a, const uint32_t* b) {
    asm volatile(
        "mma.sync.aligned.m16n8k16.row.col.f32.f16.f16.f32 "
        "{%0,%1,%2,%3}, {%4,%5,%6,%7}, {%8,%9}, {%0,%1,%2,%3};"
        : "+f"(c[0]), "+f"(c[1]), "+f"(c[2]), "+f"(c[3])
        : "r"(a[0]), "r"(a[1]), "r"(a[2]), "r"(a[3]), "r"(b[0]), "r"(b[1]));
}

// ---------------------------------------------------------------------------
// Fused setup: blocks [0,1024) convert Wh -> fp16; blocks [1024,1088) compute
// dec_features and zero ctx.
// ---------------------------------------------------------------------------
__global__ __launch_bounds__(256) void setup_kernel(
    const float* __restrict__ Wh, const float* __restrict__ s,
    const float* __restrict__ Ws, const float* __restrict__ bs,
    float* __restrict__ ctx)
{
    int blk = blockIdx.x;
    if (blk < 1024) {
        int i = blk * 256 + threadIdx.x;
        g_Wh16[i] = __float2half(Wh[i]);
    } else {
        int idx = (blk - 1024) * 256 + threadIdx.x;
        int b = idx >> 9, e = idx & 511;
        float acc = bs[e];
        const float* sp = s + b * DD;
#pragma unroll 8
        for (int d = 0; d < DD; d++) acc += sp[d] * Ws[d * DD + e];
        g_dec[idx] = acc;
        ctx[idx] = 0.0f;
    }
}

// ---------------------------------------------------------------------------
// fp16 tensor-core score GEMM, fused tanh/V-dot epilogue.  (Exact R5
// mainloop — measured 253us = 95% of the 16cyc/mma sm_100 issue floor.)
// CTA: 128 rows x full N=512, A resident fp16 in smem.
// 256 threads, 8 warps (2 M x 4 N), warp tile 64x32, BK=32 double-buffered B.
// ---------------------------------------------------------------------------
__global__ __launch_bounds__(256) void fused_score_gemm(
    const float* __restrict__ h, const float* __restrict__ cov,
    const float* __restrict__ Wc, const float* __restrict__ V)
{
    extern __shared__ char smem[];
    __half* A16 = (__half*)(smem + SM_A);
    float* sV   = (float*)(smem + SM_V);
    float* sWc  = (float*)(smem + SM_WC);
    float* sDec = (float*)(smem + SM_DEC);
    float* eSm  = (float*)(smem + SM_ESM);

    const int tid = threadIdx.x;
    const int lane = tid & 31, wid = tid >> 5;
    const int wm = wid >> 2, wn = wid & 3;           // 2 x 4 warp grid
    const int lr = lane >> 2, lc = lane & 3;
    const int row0 = blockIdx.x * 128;
    const int b = row0 >> 12;

    for (int i = tid; i < DD; i += 256) {
        sV[i] = V[i]; sWc[i] = Wc[i]; sDec[i] = g_dec[b * DD + i];
    }
    if (tid < 128) eSm[tid] = 0.0f;

    // ---- load h rows (fp32) -> convert -> resident fp16 A slab ------------
    {
        const float2* hp = (const float2*)(h + (size_t)row0 * DD);
#pragma unroll
        for (int i = 0; i < 128; i++) {
            int idx2 = tid + i * 256;
            int m = idx2 >> 8, c2 = idx2 & 255;
            float2 v = hp[(size_t)m * 256 + c2];
            *(__half2*)&A16[m * LDA + 2 * c2] = __floats2half2_rn(v.x, v.y);
        }
    }
    __syncthreads();

    const uint32_t sbB[2] = {smem_u32(smem + SM_B0), smem_u32(smem + SM_B1)};
    const uint32_t sbA = smem_u32(A16);

    float cvr[4][2];
#pragma unroll
    for (int mf = 0; mf < 4; mf++)
#pragma unroll
        for (int h2 = 0; h2 < 2; h2++)
            cvr[mf][h2] = cov[row0 + wm * 64 + mf * 16 + lr + h2 * 8];

    float acc_e[4][2];
#pragma unroll
    for (int mf = 0; mf < 4; mf++) { acc_e[mf][0] = 0.0f; acc_e[mf][1] = 0.0f; }

    // B tile loader: 32 k-rows x 128 n halves (8KB), 2 chunks of 16B/thread
    auto load_b = [&](int stage, int nb, int kt) {
#pragma unroll
        for (int i = 0; i < 2; i++) {
            int cid = tid + i * 256;                 // 0..511
            int k = cid >> 4, n8 = cid & 15;
            cp16(sbB[stage] + (k * LDB + n8 * 8) * 2,
                 g_Wh16 + (size_t)(kt * 32 + k) * DD + nb * 128 + n8 * 8);
        }
        cp_commit();
    };

    for (int nb = 0; nb < 4; nb++) {
        float acc[4][4][4];
#pragma unroll
        for (int mf = 0; mf < 4; mf++)
#pragma unroll
            for (int nf = 0; nf < 4; nf++)
#pragma unroll
                for (int c = 0; c < 4; c++) acc[mf][nf][c] = 0.0f;

        load_b(0, nb, 0);

        for (int kt = 0; kt < 16; kt++) {
            if (kt + 1 < 16) { load_b((kt + 1) & 1, nb, kt + 1); cp_wait1(); }
            else             { cp_wait0(); }
            __syncthreads();

            const uint32_t B = sbB[kt & 1];
#pragma unroll
            for (int ks = 0; ks < 2; ks++) {
                const int k0 = kt * 32 + ks * 16;    // global k for A
                uint32_t a[4][4], bb[2][4];
#pragma unroll
                for (int mf = 0; mf < 4; mf++) {
                    int row = wm * 64 + mf * 16 + (lane & 15);
                    int col = k0 + ((lane >> 4) << 3);
                    ldsm_x4(a[mf], sbA + (row * LDA + col) * 2);
                }
#pragma unroll
                for (int p = 0; p < 2; p++) {
                    int krow = ks * 16 + (lane & 15);
                    int ncol = wn * 32 + p * 16 + ((lane >> 4) << 3);
                    ldsm_x4_t(bb[p], B + (krow * LDB + ncol) * 2);
                }
#pragma unroll
                for (int mf = 0; mf < 4; mf++) {
#pragma unroll
                    for (int p = 0; p < 2; p++) {
                        mma_f16(acc[mf][2 * p],     a[mf], &bb[p][0]);
                        mma_f16(acc[mf][2 * p + 1], a[mf], &bb[p][2]);
                    }
                }
            }
            __syncthreads();
        }

        // epilogue for this N-block: accumulate V . tanh(feat)
#pragma unroll
        for (int mf = 0; mf < 4; mf++) {
#pragma unroll
            for (int h2 = 0; h2 < 2; h2++) {
                float cv = cvr[mf][h2];
                float s = 0.0f;
#pragma unroll
                for (int nf = 0; nf < 4; nf++) {
#pragma unroll
                    for (int c2 = 0; c2 < 2; c2++) {
                        int nl = nb * 128 + wn * 32 + nf * 8 + 2 * lc + c2;
                        float f = acc[mf][nf][h2 * 2 + c2] + sDec[nl] + cv * sWc[nl];
                        s += sV[nl] * tanhap(f);
                    }
                }
                acc_e[mf][h2] += s;
            }
        }
    }

    // reduce across lc quad + wn warps via smem
#pragma unroll
    for (int mf = 0; mf < 4; mf++) {
#pragma unroll
        for (int h2 = 0; h2 < 2; h2++) {
            float s = acc_e[mf][h2];
            s += __shfl_xor_sync(0xffffffffu, s, 1, 4);
            s += __shfl_xor_sync(0xffffffffu, s, 2, 4);
            if (lc == 0)
                atomicAdd(&eSm[wm * 64 + mf * 16 + lr + h2 * 8], s);
        }
    }
    __syncthreads();
    if (tid < 128) g_e_t[row0 + tid] = eSm[tid];
}

// ---------------------------------------------------------------------------
// Per-batch softmax stats: (max, sum_exp) over T.
// ---------------------------------------------------------------------------
__global__ __launch_bounds__(256) void stats_kernel()
{
    int b = blockIdx.x;
    int tid = threadIdx.x;
    const float* e = g_e_t + b * TT;
    __shared__ float red[256];
    float ev[16];
    float m = -1e30f;
#pragma unroll
    for (int k = 0; k < 16; k++) { ev[k] = e[tid + k * 256]; m = fmaxf(m, ev[k]); }
    red[tid] = m; __syncthreads();
    for (int s = 128; s > 0; s >>= 1) {
        if (tid < s) red[tid] = fmaxf(red[tid], red[tid + s]);
        __syncthreads();
    }
    float M = red[0]; __syncthreads();
    float sum = 0.0f;
#pragma unroll
    for (int k = 0; k < 16; k++) sum += expf(ev[k] - M);
    red[tid] = sum; __syncthreads();
    for (int s = 128; s > 0; s >>= 1) {
        if (tid < s) red[tid] += red[tid + s];
        __syncthreads();
    }
    if (tid == 0) g_stats[b] = make_float2(M, red[0]);
}

// ---------------------------------------------------------------------------
// Fused softmax-apply + context: per 64-token chunk, compute a = exp(e-M)/S,
// write a_out and new_coverage, then context += a^T h (float4 per thread).
// ---------------------------------------------------------------------------
__global__ __launch_bounds__(128) void context_kernel(
    const float* __restrict__ h, const float* __restrict__ cov,
    float* __restrict__ a_out, float* __restrict__ ncov_out,
    float* __restrict__ ctx)
{
    __shared__ float sa[64];
    int b  = blockIdx.x >> 6;
    int tc = blockIdx.x & 63;
    int d4 = threadIdx.x;
    int t0 = tc * 64;

    float2 st = g_stats[b];
    float M = st.x, invS = 1.0f / st.y;
    if (threadIdx.x < 64) {
        int i = b * TT + t0 + threadIdx.x;
        float a = expf(g_e_t[i] - M) * invS;
        sa[threadIdx.x] = a;
        a_out[i] = a;
        ncov_out[i] = cov[i] + a;
    }
    __syncthreads();

    const float4* hp = (const float4*)(h + ((size_t)b * TT + t0) * DD) + d4;
    float4 acc = make_float4(0.f, 0.f, 0.f, 0.f);
#pragma unroll 8
    for (int t = 0; t < 64; t++) {
        float av = sa[t];
        float4 hv = hp[(size_t)t * 128];
        acc.x += av * hv.x; acc.y += av * hv.y;
        acc.z += av * hv.z; acc.w += av * hv.w;
    }
    float* c = &ctx[b * DD + d4 * 4];
    atomicAdd(c + 0, acc.x);
    atomicAdd(c + 1, acc.y);
    atomicAdd(c + 2, acc.z);
    atomicAdd(c + 3, acc.w);
}

// ---------------------------------------------------------------------------
extern "C" void kernel_launch(void* const* d_in, const int* in_sizes, int n_in,
                              void* d_out, int out_size)
{
    const float* h   = (const float*)d_in[0];
    const float* s   = (const float*)d_in[1];
    const float* cov = (const float*)d_in[2];
    const float* Wh  = (const float*)d_in[3];
    const float* Ws  = (const float*)d_in[4];
    const float* bs  = (const float*)d_in[5];
    const float* Wc  = (const float*)d_in[6];
    const float* V   = (const float*)d_in[7];

    float* out   = (float*)d_out;
    float* ctx   = out;
    float* a_out = out + BATCH * DD;
    float* ncov  = a_out + MM;

    cudaFuncSetAttribute(fused_score_gemm,
                         cudaFuncAttributeMaxDynamicSharedMemorySize, SM_TOTAL);

    setup_kernel<<<1088, 256>>>(Wh, s, Ws, bs, ctx);
    fused_score_gemm<<<MM / 128, 256, SM_TOTAL>>>(h, cov, Wc, V);
    stats_kernel<<<BATCH, 256>>>();
    context_kernel<<<BATCH * 64, 128>>>(h, cov, a_out, ncov, ctx);
}

// round 15
// speedup vs baseline: 1.2400x; 1.0903x over previous
#include <cuda_runtime.h>
#include <cuda_fp16.h>
#include <math.h>
#include <stdint.h>

#define BATCH 32
#define TT 4096
#define DD 512
#define MM (BATCH * TT)

#define LDA 520          // A16 smem row stride in halves
#define LDB 136          // B16 smem row stride in halves

// ---------------- device scratch (no allocation allowed) -------------------
__device__ float g_p[MM];            // unnormalized exp(e_t)
__device__ float g_dec[BATCH * DD];
__device__ float g_S[BATCH];         // per-batch sum of exp
__device__ float g_ctxu[BATCH * DD]; // unnormalized context
__device__ __half g_Wh16[DD * DD];   // fp16 copy of W_h [k][n]

// ---------------- smem layout (bytes) --------------------------------------
#define SM_A     0                       // 128 * LDA * 2 = 133120
#define SM_B0    133120                  // 32 * LDB * 2 = 8704
#define SM_B1    (SM_B0 + 8704)
#define SM_V     (SM_B1 + 8704)          // float[512]
#define SM_WC    (SM_V + 2048)
#define SM_DEC   (SM_WC + 2048)
#define SM_ESM   (SM_DEC + 2048)         // float[128]
#define SM_TOTAL (SM_ESM + 512 + 512)    // 157696

// ---------------- PTX helpers ----------------------------------------------
__device__ __forceinline__ uint32_t smem_u32(const void* p) {
    uint32_t a;
    asm("{ .reg .u64 t; cvta.to.shared.u64 t, %1; cvt.u32.u64 %0, t; }" : "=r"(a) : "l"(p));
    return a;
}
__device__ __forceinline__ void cp16(uint32_t dst, const void* src) {
    asm volatile("cp.async.cg.shared.global [%0], [%1], 16;" :: "r"(dst), "l"(src));
}
__device__ __forceinline__ void cp_commit() {
    asm volatile("cp.async.commit_group;" ::: "memory");
}
__device__ __forceinline__ void cp_wait1() {
    asm volatile("cp.async.wait_group 1;" ::: "memory");
}
__device__ __forceinline__ void cp_wait0() {
    asm volatile("cp.async.wait_group 0;" ::: "memory");
}
__device__ __forceinline__ float tanhap(float x) {
    float y; asm("tanh.approx.f32 %0, %1;" : "=f"(y) : "f"(x)); return y;
}
__device__ __forceinline__ void ldsm_x4(uint32_t* r, uint32_t addr) {
    asm volatile("ldmatrix.sync.aligned.m8n8.x4.shared.b16 {%0,%1,%2,%3}, [%4];"
                 : "=r"(r[0]), "=r"(r[1]), "=r"(r[2]), "=r"(r[3]) : "r"(addr));
}
__device__ __forceinline__ void ldsm_x4_t(uint32_t* r, uint32_t addr) {
    asm volatile("ldmatrix.sync.aligned.m8n8.x4.trans.shared.b16 {%0,%1,%2,%3}, [%4];"
                 : "=r"(r[0]), "=r"(r[1]), "=r"(r[2]), "=r"(r[3]) : "r"(addr));
}
__device__ __forceinline__ void mma_f16(float* c, const uint32_t* a, const uint32_t* b) {
    asm volatile(
        "mma.sync.aligned.m16n8k16.row.col.f32.f16.f16.f32 "
        "{%0,%1,%2,%3}, {%4,%5,%6,%7}, {%8,%9}, {%0,%1,%2,%3};"
        : "+f"(c[0]), "+f"(c[1]), "+f"(c[2]), "+f"(c[3])
        : "r"(a[0]), "r"(a[1]), "r"(a[2]), "r"(a[3]), "r"(b[0]), "r"(b[1]));
}

// ---------------------------------------------------------------------------
// Fused setup: blocks [0,1024) convert Wh -> fp16; blocks [1024,1088) compute
// dec_features and zero the unnormalized-context / S accumulators.
// ---------------------------------------------------------------------------
__global__ __launch_bounds__(256) void setup_kernel(
    const float* __restrict__ Wh, const float* __restrict__ s,
    const float* __restrict__ Ws, const float* __restrict__ bs)
{
    int blk = blockIdx.x;
    if (blk < 1024) {
        int i = blk * 256 + threadIdx.x;
        g_Wh16[i] = __float2half(Wh[i]);
    } else {
        int idx = (blk - 1024) * 256 + threadIdx.x;
        int b = idx >> 9, e = idx & 511;
        float acc = bs[e];
        const float* sp = s + b * DD;
#pragma unroll 8
        for (int d = 0; d < DD; d++) acc += sp[d] * Ws[d * DD + e];
        g_dec[idx] = acc;
        g_ctxu[idx] = 0.0f;
        if (idx < BATCH) g_S[idx] = 0.0f;
    }
}

// ---------------------------------------------------------------------------
// fp16 tensor-core score GEMM + fused tanh/V-dot epilogue + fused
// unnormalized softmax/context partials (h never re-read from HBM).
// CTA: 128 rows x full N=512, A resident fp16 in smem.
// 256 threads, 8 warps (2 M x 4 N), warp tile 64x32, BK=32 double-buffered B.
// ---------------------------------------------------------------------------
__global__ __launch_bounds__(256) void fused_score_gemm(
    const float* __restrict__ h, const float* __restrict__ cov,
    const float* __restrict__ Wc, const float* __restrict__ V)
{
    extern __shared__ char smem[];
    __half* A16 = (__half*)(smem + SM_A);
    float* sV   = (float*)(smem + SM_V);
    float* sWc  = (float*)(smem + SM_WC);
    float* sDec = (float*)(smem + SM_DEC);
    float* eSm  = (float*)(smem + SM_ESM);

    const int tid = threadIdx.x;
    const int lane = tid & 31, wid = tid >> 5;
    const int wm = wid >> 2, wn = wid & 3;           // 2 x 4 warp grid
    const int lr = lane >> 2, lc = lane & 3;
    const int row0 = blockIdx.x * 128;
    const int b = row0 >> 12;

    for (int i = tid; i < DD; i += 256) {
        sV[i] = V[i]; sWc[i] = Wc[i]; sDec[i] = g_dec[b * DD + i];
    }
    if (tid < 128) eSm[tid] = 0.0f;

    // ---- load h rows (fp32) -> convert -> resident fp16 A slab ------------
    {
        const float2* hp = (const float2*)(h + (size_t)row0 * DD);
#pragma unroll
        for (int i = 0; i < 128; i++) {
            int idx2 = tid + i * 256;
            int m = idx2 >> 8, c2 = idx2 & 255;
            float2 v = hp[(size_t)m * 256 + c2];
            *(__half2*)&A16[m * LDA + 2 * c2] = __floats2half2_rn(v.x, v.y);
        }
    }
    __syncthreads();

    const uint32_t sbB[2] = {smem_u32(smem + SM_B0), smem_u32(smem + SM_B1)};
    const uint32_t sbA = smem_u32(A16);

    float cvr[4][2];
#pragma unroll
    for (int mf = 0; mf < 4; mf++)
#pragma unroll
        for (int h2 = 0; h2 < 2; h2++)
            cvr[mf][h2] = cov[row0 + wm * 64 + mf * 16 + lr + h2 * 8];

    float acc_e[4][2];
#pragma unroll
    for (int mf = 0; mf < 4; mf++) { acc_e[mf][0] = 0.0f; acc_e[mf][1] = 0.0f; }

    // B tile loader: 32 k-rows x 128 n halves (8KB), 2 chunks of 16B/thread
    auto load_b = [&](int stage, int nb, int kt) {
#pragma unroll
        for (int i = 0; i < 2; i++) {
            int cid = tid + i * 256;                 // 0..511
            int k = cid >> 4, n8 = cid & 15;
            cp16(sbB[stage] + (k * LDB + n8 * 8) * 2,
                 g_Wh16 + (size_t)(kt * 32 + k) * DD + nb * 128 + n8 * 8);
        }
        cp_commit();
    };

    for (int nb = 0; nb < 4; nb++) {
        float acc[4][4][4];
#pragma unroll
        for (int mf = 0; mf < 4; mf++)
#pragma unroll
            for (int nf = 0; nf < 4; nf++)
#pragma unroll
                for (int c = 0; c < 4; c++) acc[mf][nf][c] = 0.0f;

        load_b(0, nb, 0);

        for (int kt = 0; kt < 16; kt++) {
            if (kt + 1 < 16) { load_b((kt + 1) & 1, nb, kt + 1); cp_wait1(); }
            else             { cp_wait0(); }
            __syncthreads();

            const uint32_t B = sbB[kt & 1];
#pragma unroll
            for (int ks = 0; ks < 2; ks++) {
                const int k0 = kt * 32 + ks * 16;
                uint32_t a[4][4], bb[2][4];
#pragma unroll
                for (int mf = 0; mf < 4; mf++) {
                    int row = wm * 64 + mf * 16 + (lane & 15);
                    int col = k0 + ((lane >> 4) << 3);
                    ldsm_x4(a[mf], sbA + (row * LDA + col) * 2);
                }
#pragma unroll
                for (int p = 0; p < 2; p++) {
                    int krow = ks * 16 + (lane & 15);
                    int ncol = wn * 32 + p * 16 + ((lane >> 4) << 3);
                    ldsm_x4_t(bb[p], B + (krow * LDB + ncol) * 2);
                }
#pragma unroll
                for (int mf = 0; mf < 4; mf++) {
#pragma unroll
                    for (int p = 0; p < 2; p++) {
                        mma_f16(acc[mf][2 * p],     a[mf], &bb[p][0]);
                        mma_f16(acc[mf][2 * p + 1], a[mf], &bb[p][2]);
                    }
                }
            }
            __syncthreads();
        }

        // epilogue for this N-block: accumulate V . tanh(feat)
#pragma unroll
        for (int mf = 0; mf < 4; mf++) {
#pragma unroll
            for (int h2 = 0; h2 < 2; h2++) {
                float cv = cvr[mf][h2];
                float s = 0.0f;
#pragma unroll
                for (int nf = 0; nf < 4; nf++) {
#pragma unroll
                    for (int c2 = 0; c2 < 2; c2++) {
                        int nl = nb * 128 + wn * 32 + nf * 8 + 2 * lc + c2;
                        float f = acc[mf][nf][h2 * 2 + c2] + sDec[nl] + cv * sWc[nl];
                        s += sV[nl] * tanhap(f);
                    }
                }
                acc_e[mf][h2] += s;
            }
        }
    }

    // reduce e_t across lc quad + wn warps via smem
#pragma unroll
    for (int mf = 0; mf < 4; mf++) {
#pragma unroll
        for (int h2 = 0; h2 < 2; h2++) {
            float s = acc_e[mf][h2];
            s += __shfl_xor_sync(0xffffffffu, s, 1, 4);
            s += __shfl_xor_sync(0xffffffffu, s, 2, 4);
            if (lc == 0)
                atomicAdd(&eSm[wm * 64 + mf * 16 + lr + h2 * 8], s);
        }
    }
    __syncthreads();

    // ---- fused unnormalized softmax + context partials ---------------------
    // p = exp(e) (range-safe: |e| <= ||V||_1 ~ 18); store p, accumulate S.
    if (tid < 128) {
        float p = expf(eSm[tid]);
        eSm[tid] = p;
        g_p[row0 + tid] = p;
    }
    __syncthreads();
    if (tid < 32) {
        float s = eSm[tid] + eSm[tid + 32] + eSm[tid + 64] + eSm[tid + 96];
#pragma unroll
        for (int off = 16; off > 0; off >>= 1)
            s += __shfl_xor_sync(0xffffffffu, s, off);
        if (tid == 0) atomicAdd(&g_S[b], s);
    }
    // ctx_unnorm[b][d] += sum_t p_t * h16[t][d]  (from the resident A slab)
    {
        float cx = 0.0f, cy = 0.0f;
        const uint32_t base = 2 * tid;               // half2 column = tid
#pragma unroll 8
        for (int t = 0; t < 128; t++) {
            float p = eSm[t];
            float2 f = __half22float2(*(__half2*)&A16[t * LDA + base]);
            cx += p * f.x; cy += p * f.y;
        }
        atomicAdd(&g_ctxu[b * DD + 2 * tid],     cx);
        atomicAdd(&g_ctxu[b * DD + 2 * tid + 1], cy);
    }
}

// ---------------------------------------------------------------------------
// Finalize: a = p/S, new_cov = cov + a, ctx = ctx_unnorm/S.
// grid 512 x 256 covers MM; first 16384 threads also emit ctx.
// ---------------------------------------------------------------------------
__global__ __launch_bounds__(256) void finalize_kernel(
    const float* __restrict__ cov, float* __restrict__ a_out,
    float* __restrict__ ncov_out, float* __restrict__ ctx)
{
    int i = blockIdx.x * 256 + threadIdx.x;          // 0..131071
    int b = i >> 12;
    float invS = 1.0f / g_S[b];
    float a = g_p[i] * invS;
    a_out[i] = a;
    ncov_out[i] = cov[i] + a;
    if (i < BATCH * DD) {
        int bb = i >> 9;
        ctx[i] = g_ctxu[i] / g_S[bb];
    }
}

// ---------------------------------------------------------------------------
extern "C" void kernel_launch(void* const* d_in, const int* in_sizes, int n_in,
                              void* d_out, int out_size)
{
    const float* h   = (const float*)d_in[0];
    const float* s   = (const float*)d_in[1];
    const float* cov = (const float*)d_in[2];
    const float* Wh  = (const float*)d_in[3];
    const float* Ws  = (const float*)d_in[4];
    const float* bs  = (const float*)d_in[5];
    const float* Wc  = (const float*)d_in[6];
    const float* V   = (const float*)d_in[7];

    float* out   = (float*)d_out;
    float* ctx   = out;
    float* a_out = out + BATCH * DD;
    float* ncov  = a_out + MM;

    cudaFuncSetAttribute(fused_score_gemm,
                         cudaFuncAttributeMaxDynamicSharedMemorySize, SM_TOTAL);

    setup_kernel<<<1088, 256>>>(Wh, s, Ws, bs);
    fused_score_gemm<<<MM / 128, 256, SM_TOTAL>>>(h, cov, Wc, V);
    finalize_kernel<<<512, 256>>>(cov, a_out, ncov, ctx);
}

// round 17
// speedup vs baseline: 1.2465x; 1.0052x over previous
#include <cuda_runtime.h>
#include <cuda_fp16.h>
#include <math.h>
#include <stdint.h>

#define BATCH 32
#define TT 4096
#define DD 512
#define MM (BATCH * TT)

#define LDA 520          // A16 smem row stride in halves
#define LDB 136          // B16 smem row stride in halves

// ---------------- device scratch (no allocation allowed) -------------------
__device__ float g_p[MM];            // unnormalized exp(e_t)
__device__ float g_dec[BATCH * DD];
__device__ float g_S[BATCH];         // per-batch sum of exp
__device__ float g_ctxu[BATCH * DD]; // unnormalized context
__device__ __half g_Wh16[DD * DD];   // fp16 copy of W_h [k][n]

// ---------------- smem layout (bytes) --------------------------------------
#define SM_A     0                       // 128 * LDA * 2 = 133120
#define SM_B0    133120                  // 32 * LDB * 2 = 8704
#define SM_B1    (SM_B0 + 8704)
#define SM_V     (SM_B1 + 8704)          // float[512]
#define SM_WC    (SM_V + 2048)
#define SM_DEC   (SM_WC + 2048)
#define SM_ESM   (SM_DEC + 2048)         // float[128]
#define SM_TOTAL (SM_ESM + 512 + 512)    // 157696

// ---------------- PTX helpers ----------------------------------------------
__device__ __forceinline__ uint32_t smem_u32(const void* p) {
    uint32_t a;
    asm("{ .reg .u64 t; cvta.to.shared.u64 t, %1; cvt.u32.u64 %0, t; }" : "=r"(a) : "l"(p));
    return a;
}
__device__ __forceinline__ void cp16(uint32_t dst, const void* src) {
    asm volatile("cp.async.cg.shared.global [%0], [%1], 16;" :: "r"(dst), "l"(src));
}
__device__ __forceinline__ void cp_commit() {
    asm volatile("cp.async.commit_group;" ::: "memory");
}
__device__ __forceinline__ void cp_wait1() {
    asm volatile("cp.async.wait_group 1;" ::: "memory");
}
__device__ __forceinline__ void cp_wait0() {
    asm volatile("cp.async.wait_group 0;" ::: "memory");
}
__device__ __forceinline__ float tanhap(float x) {
    float y; asm("tanh.approx.f32 %0, %1;" : "=f"(y) : "f"(x)); return y;
}
__device__ __forceinline__ uint32_t h2_bits(__half2 v) {
    uint32_t r;
    asm("mov.b32 %0, %1;" : "=r"(r) : "r"(*(uint32_t*)&v));
    return r;
}
__device__ __forceinline__ void ldsm_x4(uint32_t* r, uint32_t addr) {
    asm volatile("ldmatrix.sync.aligned.m8n8.x4.shared.b16 {%0,%1,%2,%3}, [%4];"
                 : "=r"(r[0]), "=r"(r[1]), "=r"(r[2]), "=r"(r[3]) : "r"(addr));
}
__device__ __forceinline__ void ldsm_x4_t(uint32_t* r, uint32_t addr) {
    asm volatile("ldmatrix.sync.aligned.m8n8.x4.trans.shared.b16 {%0,%1,%2,%3}, [%4];"
                 : "=r"(r[0]), "=r"(r[1]), "=r"(r[2]), "=r"(r[3]) : "r"(addr));
}
__device__ __forceinline__ void mma_f16(float* c, const uint32_t* a, const uint32_t* b) {
    asm volatile(
        "mma.sync.aligned.m16n8k16.row.col.f32.f16.f16.f32 "
        "{%0,%1,%2,%3}, {%4,%5,%6,%7}, {%8,%9}, {%0,%1,%2,%3};"
        : "+f"(c[0]), "+f"(c[1]), "+f"(c[2]), "+f"(c[3])
        : "r"(a[0]), "r"(a[1]), "r"(a[2]), "r"(a[3]), "r"(b[0]), "r"(b[1]));
}

// ---------------------------------------------------------------------------
// Setup v2.
// Blocks [0,128): Wh -> fp16, 8 elems/thread via float4 (one wave).
// Blocks [128,192): dec_features with 4 independent accumulator chains
//                   (MLP ~32), plus zero g_ctxu / g_S.
// ---------------------------------------------------------------------------
__global__ __launch_bounds__(256) void setup_kernel(
    const float* __restrict__ Wh, const float* __restrict__ s,
    const float* __restrict__ Ws, const float* __restrict__ bs)
{
    int blk = blockIdx.x;
    if (blk < 128) {
        int base = (blk * 256 + threadIdx.x) * 8;    // 0..262136
        float4 v0 = *(const float4*)(Wh + base);
        float4 v1 = *(const float4*)(Wh + base + 4);
        uint4 packed;
        packed.x = h2_bits(__floats2half2_rn(v0.x, v0.y));
        packed.y = h2_bits(__floats2half2_rn(v0.z, v0.w));
        packed.z = h2_bits(__floats2half2_rn(v1.x, v1.y));
        packed.w = h2_bits(__floats2half2_rn(v1.z, v1.w));
        *(uint4*)(g_Wh16 + base) = packed;
    } else {
        int idx = (blk - 128) * 256 + threadIdx.x;   // 0..16383
        int b = idx >> 9, e = idx & 511;
        const float* sp = s + b * DD;
        const float* wp = Ws + e;
        float a0 = 0.f, a1 = 0.f, a2 = 0.f, a3 = 0.f;
#pragma unroll 8
        for (int d = 0; d < DD; d += 4) {
            a0 += sp[d]     * wp[(size_t)d * DD];
            a1 += sp[d + 1] * wp[(size_t)(d + 1) * DD];
            a2 += sp[d + 2] * wp[(size_t)(d + 2) * DD];
            a3 += sp[d + 3] * wp[(size_t)(d + 3) * DD];
        }
        g_dec[idx] = bs[e] + (a0 + a1) + (a2 + a3);
        g_ctxu[idx] = 0.0f;
        if (idx < BATCH) g_S[idx] = 0.0f;
    }
}

// ---------------------------------------------------------------------------
// fp16 tensor-core score GEMM + fused tanh/V-dot epilogue + fused
// unnormalized softmax/context partials (h never re-read from HBM).
// CTA: 128 rows x full N=512, A resident fp16 in smem.
// 256 threads, 8 warps (2 M x 4 N), warp tile 64x32, BK=32 double-buffered B.
// ---------------------------------------------------------------------------
__global__ __launch_bounds__(256) void fused_score_gemm(
    const float* __restrict__ h, const float* __restrict__ cov,
    const float* __restrict__ Wc, const float* __restrict__ V)
{
    extern __shared__ char smem[];
    __half* A16 = (__half*)(smem + SM_A);
    float* sV   = (float*)(smem + SM_V);
    float* sWc  = (float*)(smem + SM_WC);
    float* sDec = (float*)(smem + SM_DEC);
    float* eSm  = (float*)(smem + SM_ESM);

    const int tid = threadIdx.x;
    const int lane = tid & 31, wid = tid >> 5;
    const int wm = wid >> 2, wn = wid & 3;           // 2 x 4 warp grid
    const int lr = lane >> 2, lc = lane & 3;
    const int row0 = blockIdx.x * 128;
    const int b = row0 >> 12;

    for (int i = tid; i < DD; i += 256) {
        sV[i] = V[i]; sWc[i] = Wc[i]; sDec[i] = g_dec[b * DD + i];
    }
    if (tid < 128) eSm[tid] = 0.0f;

    // ---- load h rows (fp32) -> convert -> resident fp16 A slab ------------
    {
        const float2* hp = (const float2*)(h + (size_t)row0 * DD);
#pragma unroll
        for (int i = 0; i < 128; i++) {
            int idx2 = tid + i * 256;
            int m = idx2 >> 8, c2 = idx2 & 255;
            float2 v = hp[(size_t)m * 256 + c2];
            *(__half2*)&A16[m * LDA + 2 * c2] = __floats2half2_rn(v.x, v.y);
        }
    }
    __syncthreads();

    const uint32_t sbB[2] = {smem_u32(smem + SM_B0), smem_u32(smem + SM_B1)};
    const uint32_t sbA = smem_u32(A16);

    float cvr[4][2];
#pragma unroll
    for (int mf = 0; mf < 4; mf++)
#pragma unroll
        for (int h2 = 0; h2 < 2; h2++)
            cvr[mf][h2] = cov[row0 + wm * 64 + mf * 16 + lr + h2 * 8];

    float acc_e[4][2];
#pragma unroll
    for (int mf = 0; mf < 4; mf++) { acc_e[mf][0] = 0.0f; acc_e[mf][1] = 0.0f; }

    // B tile loader: 32 k-rows x 128 n halves (8KB), 2 chunks of 16B/thread
    auto load_b = [&](int stage, int nb, int kt) {
#pragma unroll
        for (int i = 0; i < 2; i++) {
            int cid = tid + i * 256;                 // 0..511
            int k = cid >> 4, n8 = cid & 15;
            cp16(sbB[stage] + (k * LDB + n8 * 8) * 2,
                 g_Wh16 + (size_t)(kt * 32 + k) * DD + nb * 128 + n8 * 8);
        }
        cp_commit();
    };

    for (int nb = 0; nb < 4; nb++) {
        float acc[4][4][4];
#pragma unroll
        for (int mf = 0; mf < 4; mf++)
#pragma unroll
            for (int nf = 0; nf < 4; nf++)
#pragma unroll
                for (int c = 0; c < 4; c++) acc[mf][nf][c] = 0.0f;

        load_b(0, nb, 0);

        for (int kt = 0; kt < 16; kt++) {
            if (kt + 1 < 16) { load_b((kt + 1) & 1, nb, kt + 1); cp_wait1(); }
            else             { cp_wait0(); }
            __syncthreads();

            const uint32_t B = sbB[kt & 1];
#pragma unroll
            for (int ks = 0; ks < 2; ks++) {
                const int k0 = kt * 32 + ks * 16;
                uint32_t a[4][4], bb[2][4];
#pragma unroll
                for (int mf = 0; mf < 4; mf++) {
                    int row = wm * 64 + mf * 16 + (lane & 15);
                    int col = k0 + ((lane >> 4) << 3);
                    ldsm_x4(a[mf], sbA + (row * LDA + col) * 2);
                }
#pragma unroll
                for (int p = 0; p < 2; p++) {
                    int krow = ks * 16 + (lane & 15);
                    int ncol = wn * 32 + p * 16 + ((lane >> 4) << 3);
                    ldsm_x4_t(bb[p], B + (krow * LDB + ncol) * 2);
                }
#pragma unroll
                for (int mf = 0; mf < 4; mf++) {
#pragma unroll
                    for (int p = 0; p < 2; p++) {
                        mma_f16(acc[mf][2 * p],     a[mf], &bb[p][0]);
                        mma_f16(acc[mf][2 * p + 1], a[mf], &bb[p][2]);
                    }
                }
            }
            __syncthreads();
        }

        // epilogue for this N-block: accumulate V . tanh(feat)
#pragma unroll
        for (int mf = 0; mf < 4; mf++) {
#pragma unroll
            for (int h2 = 0; h2 < 2; h2++) {
                float cv = cvr[mf][h2];
                float s = 0.0f;
#pragma unroll
                for (int nf = 0; nf < 4; nf++) {
#pragma unroll
                    for (int c2 = 0; c2 < 2; c2++) {
                        int nl = nb * 128 + wn * 32 + nf * 8 + 2 * lc + c2;
                        float f = acc[mf][nf][h2 * 2 + c2] + sDec[nl] + cv * sWc[nl];
                        s += sV[nl] * tanhap(f);
                    }
                }
                acc_e[mf][h2] += s;
            }
        }
    }

    // reduce e_t across lc quad + wn warps via smem
#pragma unroll
    for (int mf = 0; mf < 4; mf++) {
#pragma unroll
        for (int h2 = 0; h2 < 2; h2++) {
            float s = acc_e[mf][h2];
            s += __shfl_xor_sync(0xffffffffu, s, 1, 4);
            s += __shfl_xor_sync(0xffffffffu, s, 2, 4);
            if (lc == 0)
                atomicAdd(&eSm[wm * 64 + mf * 16 + lr + h2 * 8], s);
        }
    }
    __syncthreads();

    // ---- fused unnormalized softmax + context partials ---------------------
    // p = exp(e) (range-safe: |e| <= ||V||_1 ~ 18); store p, accumulate S.
    if (tid < 128) {
        float p = expf(eSm[tid]);
        eSm[tid] = p;
        g_p[row0 + tid] = p;
    }
    __syncthreads();
    if (tid < 32) {
        float s = eSm[tid] + eSm[tid + 32] + eSm[tid + 64] + eSm[tid + 96];
#pragma unroll
        for (int off = 16; off > 0; off >>= 1)
            s += __shfl_xor_sync(0xffffffffu, s, off);
        if (tid == 0) atomicAdd(&g_S[b], s);
    }
    // ctx_unnorm[b][d] += sum_t p_t * h16[t][d]  (from the resident A slab)
    {
        float cx = 0.0f, cy = 0.0f;
        const uint32_t base = 2 * tid;               // half2 column = tid
#pragma unroll 8
        for (int t = 0; t < 128; t++) {
            float p = eSm[t];
            float2 f = __half22float2(*(__half2*)&A16[t * LDA + base]);
            cx += p * f.x; cy += p * f.y;
        }
        atomicAdd(&g_ctxu[b * DD + 2 * tid],     cx);
        atomicAdd(&g_ctxu[b * DD + 2 * tid + 1], cy);
    }
}

// ---------------------------------------------------------------------------
// Finalize: a = p/S, new_cov = cov + a, ctx = ctx_unnorm/S.
// ---------------------------------------------------------------------------
__global__ __launch_bounds__(256) void finalize_kernel(
    const float* __restrict__ cov, float* __restrict__ a_out,
    float* __restrict__ ncov_out, float* __restrict__ ctx)
{
    int i = blockIdx.x * 256 + threadIdx.x;          // 0..131071
    int b = i >> 12;
    float invS = 1.0f / g_S[b];
    float a = g_p[i] * invS;
    a_out[i] = a;
    ncov_out[i] = cov[i] + a;
    if (i < BATCH * DD) {
        int bb = i >> 9;
        ctx[i] = g_ctxu[i] / g_S[bb];
    }
}

// ---------------------------------------------------------------------------
extern "C" void kernel_launch(void* const* d_in, const int* in_sizes, int n_in,
                              void* d_out, int out_size)
{
    const float* h   = (const float*)d_in[0];
    const float* s   = (const float*)d_in[1];
    const float* cov = (const float*)d_in[2];
    const float* Wh  = (const float*)d_in[3];
    const float* Ws  = (const float*)d_in[4];
    const float* bs  = (const float*)d_in[5];
    const float* Wc  = (const float*)d_in[6];
    const float* V   = (const float*)d_in[7];

    float* out   = (float*)d_out;
    float* ctx   = out;
    float* a_out = out + BATCH * DD;
    float* ncov  = a_out + MM;

    cudaFuncSetAttribute(fused_score_gemm,
                         cudaFuncAttributeMaxDynamicSharedMemorySize, SM_TOTAL);

    setup_kernel<<<192, 256>>>(Wh, s, Ws, bs);
    fused_score_gemm<<<MM / 128, 256, SM_TOTAL>>>(h, cov, Wc, V);
    finalize_kernel<<<512, 256>>>(cov, a_out, ncov, ctx);
}